// round 12
// baseline (speedup 1.0000x reference)
#include <cuda_runtime.h>

// out = clip(x + laplace * mask, 0, 1), elementwise, 38,535,168 fp32.
// HBM-roofline streaming kernel: 3 reads + 1 write, 616.6 MB irreducible.
// R9: final knob — block size 512 (structure identical to R6's measured-best
// unguarded VPT=2 float4 path). Sweep so far (kernel us):
//   VPT1/256t guarded: 84.3 | VPT2/256t pred: 83.0 | VPT4/256t: 83.7
//   VPT2/256t unguarded: 83.2 | 256-bit/256t: 84.2   -> all ~7.0 TB/s.

#define VPT 2       // float4s per thread
#define THREADS 512

// Bulk kernel: every thread owns VPT full float4s, no bounds checks.
__global__ void rrn_clip_bulk(const float4* __restrict__ x,
                              const float4* __restrict__ lap,
                              const float4* __restrict__ mask,
                              float4* __restrict__ out) {
    int base = (blockIdx.x * THREADS) * VPT + threadIdx.x;

    float4 xv[VPT], lv[VPT], mv[VPT];
    #pragma unroll
    for (int j = 0; j < VPT; j++) {
        int i = base + j * THREADS;
        xv[j] = __ldcs(x + i);
        lv[j] = __ldcs(lap + i);
        mv[j] = __ldcs(mask + i);
    }
    #pragma unroll
    for (int j = 0; j < VPT; j++) {
        int i = base + j * THREADS;
        float4 r;
        r.x = __saturatef(fmaf(lv[j].x, mv[j].x, xv[j].x));
        r.y = __saturatef(fmaf(lv[j].y, mv[j].y, xv[j].y));
        r.z = __saturatef(fmaf(lv[j].z, mv[j].z, xv[j].z));
        r.w = __saturatef(fmaf(lv[j].w, mv[j].w, xv[j].w));
        __stcs(out + i, r);
    }
}

// Generic scalar remainder (covers non-divisible n; not launched for this shape).
__global__ void rrn_clip_rem(const float* __restrict__ x,
                             const float* __restrict__ lap,
                             const float* __restrict__ mask,
                             float* __restrict__ out,
                             int start, int n) {
    int i = start + blockIdx.x * blockDim.x + threadIdx.x;
    if (i >= n) return;
    out[i] = __saturatef(fmaf(__ldcs(lap + i), __ldcs(mask + i), __ldcs(x + i)));
}

extern "C" void kernel_launch(void* const* d_in, const int* in_sizes, int n_in,
                              void* d_out, int out_size) {
    // metadata order: x, eps (dead scalar), laplace_noise, mask
    const float* x    = (const float*)d_in[0];
    const float* lap  = (const float*)d_in[2];
    const float* mask = (const float*)d_in[3];
    float* out        = (float*)d_out;

    int n = in_sizes[0];
    const int elems_per_block = THREADS * VPT * 4;   // 4096 floats per block
    int full_blocks = n / elems_per_block;           // 9408 for this shape, rem=0

    if (full_blocks > 0) {
        rrn_clip_bulk<<<full_blocks, THREADS>>>(
            (const float4*)x, (const float4*)lap, (const float4*)mask,
            (float4*)out);
    }
    int done = full_blocks * elems_per_block;
    int rem = n - done;
    if (rem > 0) {
        int blocks = (rem + THREADS - 1) / THREADS;
        rrn_clip_rem<<<blocks, THREADS>>>(x, lap, mask, out, done, n);
    }
}